// round 3
// baseline (speedup 1.0000x reference)
#include <cuda_runtime.h>

#define B_   4096
#define T_   64
#define OBS_ 64
#define H_   64
#define A_   8
#define S_   201
#define G_   16
#define NTHR 128

typedef unsigned long long u64;
typedef unsigned int u32;

// ---- packed f32x2 helpers (sm_100+ PTX) ----
__device__ __forceinline__ u64 fma2(u64 a, u64 b, u64 c) {
    u64 d;
    asm("fma.rn.f32x2 %0, %1, %2, %3;" : "=l"(d) : "l"(a), "l"(b), "l"(c));
    return d;
}
__device__ __forceinline__ u64 pack2(float x, float y) {
    u64 d;
    asm("mov.b64 %0, {%1, %2};" : "=l"(d) : "r"(__float_as_uint(x)), "r"(__float_as_uint(y)));
    return d;
}
__device__ __forceinline__ float2 unpack2(u64 a) {
    u32 lo, hi;
    asm("mov.b64 {%0, %1}, %2;" : "=r"(lo), "=r"(hi) : "l"(a));
    float2 r; r.x = __uint_as_float(lo); r.y = __uint_as_float(hi);
    return r;
}

// Exact clone of XLA's f32 fast-tanh (Eigen rational approximation), which is
// what the JAX reference lowers tanh to on both CPU and GPU backends:
//   clamp to +-7.90531110763549805, Horner in x^2 with FMA, precise divide,
//   and passthrough for |x| < 0.0004. Matching this bit-for-bit removes the
//   dominant perturbation that was flipping argmax decisions.
__device__ __forceinline__ float tanh_xla(float x) {
    float xc = fminf(fmaxf(x, -7.90531110763549805f), 7.90531110763549805f);
    float x2 = xc * xc;
    float p = -2.76076847742355e-16f;
    p = __fmaf_rn(p, x2, 2.00018790482477e-13f);
    p = __fmaf_rn(p, x2, -8.60467152213735e-11f);
    p = __fmaf_rn(p, x2, 5.12229709037114e-08f);
    p = __fmaf_rn(p, x2, 1.48572235717979e-05f);
    p = __fmaf_rn(p, x2, 6.37261928875436e-04f);
    p = __fmaf_rn(p, x2, 4.89352455891786e-03f);
    float num = xc * p;
    float q = 1.19825839466702e-06f;
    q = __fmaf_rn(q, x2, 1.18534705686654e-04f);
    q = __fmaf_rn(q, x2, 2.26843463243900e-03f);
    q = __fmaf_rn(q, x2, 4.89352518554385e-03f);
    float r = __fdiv_rn(num, q);
    return (fabsf(x) < 0.0004f) ? x : r;
}

// output layout (flattened tuple, in return order, float32):
//   logitss  [B,T,A]   @ 0
//   values   [T*B]     @ OFF_VAL   (time-major)
//   stack    [B,S,H]   @ OFF_STK
//   ptrs     [B]       @ OFF_PTR
#define OFF_VAL ((size_t)B_ * T_ * A_)
#define OFF_STK (OFF_VAL + (size_t)T_ * B_)
#define OFF_PTR (OFF_STK + (size_t)B_ * S_ * H_)

// shared memory layout (floats)
#define SM_W1T   0                       // 128*64
#define SM_W2T   (SM_W1T + 8192)         // 64*64
#define SM_WHT   (SM_W2T + 4096)         // 64*12
#define SM_B1    (SM_WHT + 768)          // 64
#define SM_B2    (SM_B1 + 64)            // 64
#define SM_BH    (SM_B2 + 64)            // 12
#define SM_IN    (SM_BH + 12)            // 128*18
#define SM_HT    (SM_IN + 2304)          // 64*18
#define SM_PT    (SM_HT + 1152)          // 64*18
#define SM_PROW  (SM_PT + 1152)          // 16*68
#define SM_LS    (SM_PROW + 1088)        // 16*4
#define SM_INTS  (SM_LS + 64)            // ptrS(16) ptrOld(16) opS(16) wbits(112) as ints
#define SMEM_BYTES ((SM_INTS + 160) * 4)

__global__ void __launch_bounds__(NTHR, 2) stacknet_kernel(
    const float* __restrict__ x,        const float* __restrict__ stack_in,
    const int*   __restrict__ ptr_in,
    const float* __restrict__ W1,  const float* __restrict__ b1,
    const float* __restrict__ W2,  const float* __restrict__ b2,
    const float* __restrict__ Ws,  const float* __restrict__ bsv,
    const float* __restrict__ Wp,  const float* __restrict__ bp,
    const float* __restrict__ Wv,  const float* __restrict__ bv,
    float* __restrict__ out)
{
    extern __shared__ float sm[];
    float* W1t  = sm + SM_W1T;
    float* W2t  = sm + SM_W2T;
    float* Wht  = sm + SM_WHT;
    float* b1s  = sm + SM_B1;
    float* b2s  = sm + SM_B2;
    float* bhs  = sm + SM_BH;
    float* InT  = sm + SM_IN;     // [128][18]  concat(x_t, top) transposed
    float* Ht   = sm + SM_HT;     // [64][18]
    float* Pt   = sm + SM_PT;     // [64][18]
    float* Prow = sm + SM_PROW;   // [16][68]   p row-major for stack writes
    float* Ls   = sm + SM_LS;     // [16][4]    stack-head logits
    int*   ptrS    = (int*)(sm + SM_INTS);
    int*   ptrOldS = ptrS + 16;
    int*   opS     = ptrOldS + 16;
    u32*   wbits   = (u32*)(opS + 16);   // [16][7] written-row bitmap

    const int tid  = threadIdx.x;
    const int base = blockIdx.x * G_;

    // ---- load weights (transposed for conflict-free vector LDS) ----
    for (int i = tid; i < 8192; i += NTHR) { int j = i >> 7, k = i & 127; W1t[k * 64 + j] = W1[i]; }
    for (int i = tid; i < 4096; i += NTHR) { int j = i >> 6, k = i & 63;  W2t[k * 64 + j] = W2[i]; }
    for (int i = tid; i < 192;  i += NTHR) { int h = i >> 6, k = i & 63;  Wht[k * 12 + h] = Ws[i]; }
    for (int i = tid; i < 512;  i += NTHR) { int h = 3 + (i >> 6), k = i & 63; Wht[k * 12 + h] = Wp[i]; }
    for (int i = tid; i < 64;   i += NTHR) { Wht[i * 12 + 11] = Wv[i]; }
    if (tid < 64) { b1s[tid] = b1[tid]; b2s[tid] = b2[tid]; }
    if (tid < 3)               bhs[tid] = bsv[tid];
    if (tid >= 3 && tid < 11)  bhs[tid] = bp[tid - 3];
    if (tid == 11)             bhs[11]  = bv[0];
    for (int i = tid; i < G_ * 7; i += NTHR) wbits[i] = 0;
    if (tid < G_) ptrS[tid] = ptr_in[base + tid];
    __syncthreads();

    const int e   = tid >> 3;       // batch element within block (for IO stages)
    const int seg = tid & 7;        // 8-float segment of a 64-float row
    const int r   = tid & 7;        // row-pair index for matmul tile (rows 2r,2r+1)
    const int cc  = tid >> 3;       // col-quad index for matmul tile (cols 4cc..4cc+3)

    // ---- initial prefetch: x_0 and top = stack_in[b][ptr0] ----
    float4 xr0, xr1, c0, c1;
    {
        const float4* xs = (const float4*)(x + (size_t)(base + e) * T_ * OBS_ + seg * 8);
        xr0 = xs[0]; xr1 = xs[1];
        int p0 = ptrS[e];
        const float4* ss = (const float4*)(stack_in + ((size_t)(base + e) * S_ + p0) * H_ + seg * 8);
        c0 = ss[0]; c1 = ss[1];
    }

    for (int t = 0; t < T_; ++t) {
        // scatter x_t and top into InT (transposed, stride 18)
        const float* xf0 = (const float*)&xr0; const float* xf1 = (const float*)&xr1;
        const float* cf0 = (const float*)&c0;  const float* cf1 = (const float*)&c1;
        #pragma unroll
        for (int i = 0; i < 4; ++i) {
            InT[(seg * 8 + i) * 18 + e]          = xf0[i];
            InT[(seg * 8 + 4 + i) * 18 + e]      = xf1[i];
            InT[(64 + seg * 8 + i) * 18 + e]     = cf0[i];
            InT[(64 + seg * 8 + 4 + i) * 18 + e] = cf1[i];
        }
        __syncthreads();

        // prefetch x_{t+1} (hidden under W1 compute)
        if (t + 1 < T_) {
            const float4* xs = (const float4*)(x + (size_t)(base + e) * T_ * OBS_
                                                 + (size_t)(t + 1) * OBS_ + seg * 8);
            xr0 = xs[0]; xr1 = xs[1];
        }

        // ---- W1: [16 x 128] @ [128 x 64], 2x4 tile, f32x2 accumulate ----
        u64 a00 = 0ull, a01 = 0ull, a10 = 0ull, a11 = 0ull;
        #pragma unroll 8
        for (int k = 0; k < 128; ++k) {
            float2 in = *(const float2*)&InT[k * 18 + 2 * r];
            u64 w01 = *(const u64*)&W1t[k * 64 + 4 * cc];
            u64 w23 = *(const u64*)&W1t[k * 64 + 4 * cc + 2];
            u64 ax = pack2(in.x, in.x), ay = pack2(in.y, in.y);
            a00 = fma2(ax, w01, a00); a01 = fma2(ax, w23, a01);
            a10 = fma2(ay, w01, a10); a11 = fma2(ay, w23, a11);
        }
        {
            float2 v0 = unpack2(a00), v1 = unpack2(a01), v2 = unpack2(a10), v3 = unpack2(a11);
            float vals[8] = {v0.x, v0.y, v1.x, v1.y, v2.x, v2.y, v3.x, v3.y};
            int j0 = 4 * cc;
            #pragma unroll
            for (int i = 0; i < 8; ++i) {
                int j = j0 + (i & 3), g = 2 * r + (i >> 2);
                Ht[j * 18 + g] = tanh_xla(vals[i] + b1s[j]);
            }
        }
        __syncthreads();

        // ---- W2: [16 x 64] @ [64 x 64] ----
        a00 = a01 = a10 = a11 = 0ull;
        #pragma unroll 8
        for (int k = 0; k < 64; ++k) {
            float2 in = *(const float2*)&Ht[k * 18 + 2 * r];
            u64 w01 = *(const u64*)&W2t[k * 64 + 4 * cc];
            u64 w23 = *(const u64*)&W2t[k * 64 + 4 * cc + 2];
            u64 ax = pack2(in.x, in.x), ay = pack2(in.y, in.y);
            a00 = fma2(ax, w01, a00); a01 = fma2(ax, w23, a01);
            a10 = fma2(ay, w01, a10); a11 = fma2(ay, w23, a11);
        }
        {
            float2 v0 = unpack2(a00), v1 = unpack2(a01), v2 = unpack2(a10), v3 = unpack2(a11);
            float vals[8] = {v0.x, v0.y, v1.x, v1.y, v2.x, v2.y, v3.x, v3.y};
            int j0 = 4 * cc;
            #pragma unroll
            for (int i = 0; i < 8; ++i) {
                int j = j0 + (i & 3), g = 2 * r + (i >> 2);
                float p = tanh_xla(vals[i] + b2s[j]);
                Pt[j * 18 + g]   = p;
                Prow[g * 68 + j] = p;
            }
        }
        __syncthreads();

        // ---- heads: 16 elems x 12 dots of length 64, bias added LAST
        //      (matches reference's `p @ W.T + b` ordering) ----
        for (int o = tid; o < G_ * 12; o += NTHR) {
            int ee = o / 12, h = o - 12 * ee;
            float acc = 0.0f;
            #pragma unroll 8
            for (int k = 0; k < 64; ++k) acc = __fmaf_rn(Pt[k * 18 + ee], Wht[k * 12 + h], acc);
            acc += bhs[h];
            if (h < 3)       Ls[ee * 4 + h] = acc;
            else if (h < 11) out[((size_t)(base + ee) * T_ + t) * A_ + (h - 3)] = acc;
            else             out[OFF_VAL + (size_t)t * B_ + (base + ee)] = acc;
        }
        __syncthreads();

        // ---- argmax + pointer update (one thread per element) ----
        // argmax(softmax(l)) == argmax(l) with first-index tie-break.
        if (tid < G_) {
            int ee = tid;
            float l0 = Ls[ee * 4], l1 = Ls[ee * 4 + 1], l2 = Ls[ee * 4 + 2];
            int op = 0; float bst = l0;
            if (l1 > bst) { bst = l1; op = 1; }
            if (l2 > bst) { op = 2; }
            int p = ptrS[ee];
            ptrOldS[ee] = p; opS[ee] = op;
            int np = p + op - 1; np = np < 0 ? 0 : np;
            ptrS[ee] = np;
            if (op == 2) wbits[ee * 7 + (p >> 5)] |= (1u << (p & 31));
        }
        __syncthreads();

        // ---- push write-through + next-top reload (invariant: top == stack[ptr]) ----
        {
            if (opS[e] == 2) {
                float4* dst = (float4*)(out + OFF_STK
                    + ((size_t)(base + e) * S_ + ptrOldS[e]) * H_ + seg * 8);
                const float4* srcp = (const float4*)&Prow[e * 68 + seg * 8];
                dst[0] = srcp[0]; dst[1] = srcp[1];
            }
            if (t + 1 < T_) {
                int row = ptrS[e];
                bool written = (wbits[e * 7 + (row >> 5)] >> (row & 31)) & 1u;
                const float* sbase = written ? (out + OFF_STK) : stack_in;
                const float4* ss = (const float4*)(sbase
                    + ((size_t)(base + e) * S_ + row) * H_ + seg * 8);
                c0 = ss[0]; c1 = ss[1];
            }
        }
    }

    // final pointers (as float, per assumed output dtype)
    if (tid < G_) out[OFF_PTR + base + tid] = (float)ptrS[tid];
    __syncthreads();

    // epilogue: copy never-written stack rows from input (pushed rows were
    // written through during the scan, latest value already in place)
    for (int it = tid; it < G_ * S_; it += NTHR) {
        int ee = it / S_, rr = it - S_ * ee;
        if (!((wbits[ee * 7 + (rr >> 5)] >> (rr & 31)) & 1u)) {
            const float4* src = (const float4*)(stack_in + ((size_t)(base + ee) * S_ + rr) * H_);
            float4* dst = (float4*)(out + OFF_STK + ((size_t)(base + ee) * S_ + rr) * H_);
            #pragma unroll
            for (int q = 0; q < 16; ++q) dst[q] = src[q];
        }
    }
}

extern "C" void kernel_launch(void* const* d_in, const int* in_sizes, int n_in,
                              void* d_out, int out_size) {
    (void)in_sizes; (void)n_in; (void)out_size;
    cudaFuncSetAttribute(stacknet_kernel, cudaFuncAttributeMaxDynamicSharedMemorySize, SMEM_BYTES);
    const float* x        = (const float*)d_in[0];
    const float* stack_in = (const float*)d_in[1];
    const int*   ptrs     = (const int*)  d_in[2];
    const float* W1 = (const float*)d_in[3];  const float* b1 = (const float*)d_in[4];
    const float* W2 = (const float*)d_in[5];  const float* b2 = (const float*)d_in[6];
    const float* Ws = (const float*)d_in[7];  const float* bs = (const float*)d_in[8];
    const float* Wp = (const float*)d_in[9];  const float* bp = (const float*)d_in[10];
    const float* Wv = (const float*)d_in[11]; const float* bv = (const float*)d_in[12];
    stacknet_kernel<<<B_ / G_, NTHR, SMEM_BYTES>>>(
        x, stack_in, ptrs, W1, b1, W2, b2, Ws, bs, Wp, bp, Wv, bv, (float*)d_out);
}